// round 7
// baseline (speedup 1.0000x reference)
#include <cuda_runtime.h>
#include <cuda_bf16.h>
#include <cstdint>
#include <cstddef>

// Problem: B=8, Q=2048, K=2048, D=256, TOP_K=64
#define B_DIM 8
#define Q_DIM 2048
#define K_DIM 2048
#define D_DIM 256
#define NEGV (-1000000.0f)

// 8*2048*2048 fp32 scores scratch (134 MB) — static device global (no allocs allowed).
__device__ float g_scores[(size_t)B_DIM * Q_DIM * K_DIM];

// ============================ helpers ============================

__device__ __forceinline__ uint32_t smem_u32(const void* p) {
    uint32_t a;
    asm("{ .reg .u64 t; cvta.to.shared.u64 t, %1; cvt.u32.u64 %0, t; }" : "=r"(a) : "l"(p));
    return a;
}

__device__ __forceinline__ uint32_t pack_bf2(float a, float b) {
    __nv_bfloat16 ha = __float2bfloat16(a);
    __nv_bfloat16 hb = __float2bfloat16(b);
    return (uint32_t)__bfloat16_as_ushort(ha) | ((uint32_t)__bfloat16_as_ushort(hb) << 16);
}
__device__ __forceinline__ float bf_res(float x) {
    return x - __bfloat162float(__float2bfloat16(x));
}

// ldmatrix.x4 from a SW128-swizzled [rows x 64 bf16] tile (128 bytes/row).
__device__ __forceinline__ void ldsm4(uint32_t sbase, int row, int kbyte, uint32_t r[4]) {
    uint32_t off = (uint32_t)(row << 7) + (uint32_t)kbyte;
    uint32_t sw = off ^ ((off >> 3) & 0x70);
    asm volatile("ldmatrix.sync.aligned.m8n8.x4.shared.b16 {%0,%1,%2,%3}, [%4];"
                 : "=r"(r[0]), "=r"(r[1]), "=r"(r[2]), "=r"(r[3])
                 : "r"(sbase + sw));
}

__device__ __forceinline__ void mma16816(float d[4], const uint32_t a[4],
                                         uint32_t b0, uint32_t b1) {
    asm volatile(
        "mma.sync.aligned.m16n8k16.row.col.f32.bf16.bf16.f32 "
        "{%0,%1,%2,%3}, {%4,%5,%6,%7}, {%8,%9}, {%0,%1,%2,%3};"
        : "+f"(d[0]), "+f"(d[1]), "+f"(d[2]), "+f"(d[3])
        : "r"(a[0]), "r"(a[1]), "r"(a[2]), "r"(a[3]), "r"(b0), "r"(b1));
}

// ============================ Kernel 1: scores = Q·K^T / 16 ============================
// fp32 emulated as 3x bf16 HMMA passes (Ah·Bh + Ah·Bl + Al·Bh). CTA tile 128(M) x 128(N),
// K loop in 4 chunks of 64 floats. 8 warps (4m x 2n), warp tile 32x64, mma.m16n8k16.

#define SM_A_HI 0u
#define SM_A_LO 16384u
#define SM_B_HI 32768u
#define SM_B_LO 49152u
#define SMEM_BYTES 65536

__device__ __forceinline__ void gemm_pass(uint32_t sA, uint32_t sB, int wm, int wn,
                                          int lane, float acc[2][8][4]) {
    const int lrow = lane & 15;
    const int lkb = (lane >> 4) << 4;   // 0 or 16 bytes
    #pragma unroll
    for (int ks = 0; ks < 4; ++ks) {
        const int kbyte = (ks << 5) + lkb;
        uint32_t a[2][4];
        ldsm4(sA, (wm << 5) + lrow, kbyte, a[0]);
        ldsm4(sA, (wm << 5) + 16 + lrow, kbyte, a[1]);
        uint32_t bb[4][4];
        #pragma unroll
        for (int np = 0; np < 4; ++np)
            ldsm4(sB, (wn << 6) + (np << 4) + lrow, kbyte, bb[np]);
        #pragma unroll
        for (int mt = 0; mt < 2; ++mt)
            #pragma unroll
            for (int nt = 0; nt < 8; ++nt)
                mma16816(acc[mt][nt], a[mt], bb[nt >> 1][nt & 1], bb[nt >> 1][2 + (nt & 1)]);
    }
}

__global__ void __launch_bounds__(256, 2)
sa_gemm_scores(const float* __restrict__ Qg, const float* __restrict__ Kg) {
    extern __shared__ char smem[];
    const int tid = threadIdx.x;
    const int wid = tid >> 5;
    const int lane = tid & 31;
    const int wm = wid & 3;
    const int wn = wid >> 2;
    const uint32_t sb = smem_u32(smem);

    const int b = blockIdx.z;
    const int m0 = blockIdx.y << 7;
    const int n0 = blockIdx.x << 7;
    const float* Ag = Qg + ((size_t)(b * Q_DIM + m0)) * D_DIM;
    const float* Bg = Kg + ((size_t)(b * K_DIM + n0)) * D_DIM;

    float acc[2][8][4];
    #pragma unroll
    for (int mt = 0; mt < 2; ++mt)
        #pragma unroll
        for (int nt = 0; nt < 8; ++nt)
            #pragma unroll
            for (int j = 0; j < 4; ++j) acc[mt][nt][j] = 0.f;

    #pragma unroll 1
    for (int c = 0; c < 4; ++c) {
        if (c) __syncthreads();

        #pragma unroll
        for (int t = 0; t < 8; ++t) {
            int idx = tid + (t << 8);
            int row = idx >> 4;
            int c4  = (idx & 15) << 2;
            size_t go = (size_t)row * D_DIM + (c << 6) + c4;
            float4 va = *(const float4*)(Ag + go);
            float4 vb = *(const float4*)(Bg + go);
            uint32_t off = (uint32_t)(row << 7) + (uint32_t)(c4 << 1);
            uint32_t sw = off ^ ((off >> 3) & 0x70);

            *(uint32_t*)(smem + SM_A_HI + sw)     = pack_bf2(va.x, va.y);
            *(uint32_t*)(smem + SM_A_HI + sw + 4) = pack_bf2(va.z, va.w);
            *(uint32_t*)(smem + SM_A_LO + sw)     = pack_bf2(bf_res(va.x), bf_res(va.y));
            *(uint32_t*)(smem + SM_A_LO + sw + 4) = pack_bf2(bf_res(va.z), bf_res(va.w));

            *(uint32_t*)(smem + SM_B_HI + sw)     = pack_bf2(vb.x, vb.y);
            *(uint32_t*)(smem + SM_B_HI + sw + 4) = pack_bf2(vb.z, vb.w);
            *(uint32_t*)(smem + SM_B_LO + sw)     = pack_bf2(bf_res(vb.x), bf_res(vb.y));
            *(uint32_t*)(smem + SM_B_LO + sw + 4) = pack_bf2(bf_res(vb.z), bf_res(vb.w));
        }
        __syncthreads();

        gemm_pass(sb + SM_A_HI, sb + SM_B_HI, wm, wn, lane, acc);  // hi*hi
        gemm_pass(sb + SM_A_HI, sb + SM_B_LO, wm, wn, lane, acc);  // hi*lo
        gemm_pass(sb + SM_A_LO, sb + SM_B_HI, wm, wn, lane, acc);  // lo*hi
    }

    float* gout = g_scores + ((size_t)(b * Q_DIM + m0)) * K_DIM + n0;
    const int rb = (wm << 5) + (lane >> 2);
    const int cb = (wn << 6) + ((lane & 3) << 1);
    #pragma unroll
    for (int mt = 0; mt < 2; ++mt)
        #pragma unroll
        for (int nt = 0; nt < 8; ++nt) {
            int r = rb + (mt << 4);
            int cc = cb + (nt << 3);
            float2 v0 = make_float2(acc[mt][nt][0] * 0.0625f, acc[mt][nt][1] * 0.0625f);
            float2 v1 = make_float2(acc[mt][nt][2] * 0.0625f, acc[mt][nt][3] * 0.0625f);
            *(float2*)&gout[(size_t)r * K_DIM + cc] = v0;
            *(float2*)&gout[(size_t)(r + 8) * K_DIM + cc] = v1;
        }
}

// ============================ Kernel 2 ============================
// Per (b,q) row: mask -> approx top-64 threshold (radix select on valid entries) ->
// exact fp32 recompute of boundary-ambiguous entries -> reference-exact selection
// (score >= kth, ties kept) -> softmax -> compacted sparse AV.

__device__ __forceinline__ unsigned f2srt(float f) {
    unsigned u = __float_as_uint(f);
    return (u & 0x80000000u) ? ~u : (u | 0x80000000u);
}
__device__ __forceinline__ float srt2f(unsigned s) {
    unsigned u = (s & 0x80000000u) ? (s & 0x7FFFFFFFu) : ~s;
    return __uint_as_float(u);
}

#define AMB_CAP 96
#define BAND 1e-3f

__global__ void __launch_bounds__(128)
sa_topk_softmax_av(const float* __restrict__ Qg, const float* __restrict__ Kg,
                   const float* __restrict__ Vg, const int* __restrict__ vlens,
                   float* __restrict__ out) {
    __shared__ float    s_wv[2048];
    __shared__ int      s_idx[2048];
    __shared__ float    s_qf[256];
    __shared__ unsigned s_hist[256];
    __shared__ float    s_red[128];
    __shared__ int      s_amb_idx[AMB_CAP];
    __shared__ float    s_amb_v[AMB_CAP];
    __shared__ float    s_amb_ex[AMB_CAP];
    __shared__ unsigned s_pref;
    __shared__ int      s_r;
    __shared__ int      s_cnt;
    __shared__ int      s_namb;
    __shared__ float    s_thex;

    const int tid = threadIdx.x;
    const int lane = tid & 31;
    const int wrp = tid >> 5;
    const int rowid = blockIdx.x;          // b*2048 + q
    const int b = rowid >> 11;
    const int vlen = vlens[b];
    const float* sc = g_scores + (size_t)rowid * K_DIM;
    const float* qrow = Qg + (size_t)rowid * D_DIM;

    // Stage Q row for exact recompute.
    s_qf[tid] = qrow[tid];
    s_qf[tid + 128] = qrow[tid + 128];

    // Load masked scores (16/thread, coalesced); row max.
    float vreg[16];
    float lmax = NEGV;
    #pragma unroll
    for (int i = 0; i < 16; ++i) {
        int k = tid + (i << 7);
        float v = sc[k];
        if (k >= vlen) v = NEGV;
        vreg[i] = v;
        lmax = fmaxf(lmax, v);
    }
    s_red[tid] = lmax;
    if (tid == 0) { s_cnt = 0; s_namb = 0; s_pref = 0u; s_r = 64; }
    __syncthreads();
    #pragma unroll
    for (int s = 64; s > 0; s >>= 1) {
        if (tid < s) s_red[tid] = fmaxf(s_red[tid], s_red[tid + s]);
        __syncthreads();
    }
    const float m = s_red[0];

    if (vlen >= 64) {
        // ---- approx kth via MSB-first radix select over valid entries only ----
        unsigned prefmask = 0u;
        for (int shift = 24; shift >= 0; shift -= 8) {
            s_hist[tid] = 0u;
            s_hist[tid + 128] = 0u;
            __syncthreads();
            const unsigned pref = s_pref;
            #pragma unroll
            for (int i = 0; i < 16; ++i) {
                int k = tid + (i << 7);
                if (k < vlen) {
                    unsigned u = f2srt(vreg[i]);
                    if ((u & prefmask) == pref) atomicAdd(&s_hist[(u >> shift) & 255], 1u);
                }
            }
            __syncthreads();
            if (tid == 0) {
                int r = s_r;
                unsigned acc = 0;
                int d = 255;
                for (; d >= 0; --d) {
                    unsigned h = s_hist[d];
                    if (acc + h >= (unsigned)r) break;
                    acc += h;
                }
                s_pref |= ((unsigned)d) << shift;
                s_r = r - (int)acc;
            }
            __syncthreads();
            prefmask |= 0xFFu << shift;
        }
        const float t = srt2f(s_pref);   // approx 64th-largest valid score

        // ---- classify: certain-in (push now) / ambiguous (collect) ----
        #pragma unroll
        for (int i = 0; i < 16; ++i) {
            float v = vreg[i];
            if (v > t + BAND) {
                int p = atomicAdd(&s_cnt, 1);
                s_idx[p] = tid + (i << 7);
                s_wv[p] = expf(v - m);
            } else if (v >= t - BAND) {
                int p = atomicAdd(&s_namb, 1);
                if (p < AMB_CAP) {
                    s_amb_idx[p] = tid + (i << 7);
                    s_amb_v[p] = v;
                }
            }
        }
        __syncthreads();
        const int c_in = s_cnt;
        const int namb = min(s_namb, AMB_CAP);

        // ---- exact fp32 scores for ambiguous entries (one warp per entry) ----
        for (int j = wrp; j < namb; j += 4) {
            const float* kr = Kg + ((size_t)(b * K_DIM + s_amb_idx[j])) * D_DIM;
            float4 k0 = *(const float4*)(kr + lane * 4);
            float4 k1 = *(const float4*)(kr + 128 + lane * 4);
            float4 q0 = *(const float4*)(s_qf + lane * 4);
            float4 q1 = *(const float4*)(s_qf + 128 + lane * 4);
            float s = q0.x * k0.x;
            s = fmaf(q0.y, k0.y, s); s = fmaf(q0.z, k0.z, s); s = fmaf(q0.w, k0.w, s);
            s = fmaf(q1.x, k1.x, s); s = fmaf(q1.y, k1.y, s);
            s = fmaf(q1.z, k1.z, s); s = fmaf(q1.w, k1.w, s);
            #pragma unroll
            for (int o = 16; o > 0; o >>= 1) s += __shfl_xor_sync(0xFFFFFFFFu, s, o);
            if (lane == 0) s_amb_ex[j] = s * 0.0625f;
        }
        __syncthreads();

        // ---- exact (need)-th largest among ambiguous; reference tie semantics ----
        if (tid == 0) {
            int need = 64 - c_in;   // >= 1 (at most 63 entries strictly above t)
            float th = s_amb_ex[0];
            for (int j = 0; j < namb; ++j) {
                float x = s_amb_ex[j];
                int gt = 0, ge = 0;
                for (int l = 0; l < namb; ++l) {
                    gt += (s_amb_ex[l] > x);
                    ge += (s_amb_ex[l] >= x);
                }
                if (gt < need && ge >= need) { th = x; break; }
            }
            s_thex = th;
        }
        __syncthreads();
        const float th = s_thex;
        for (int j = tid; j < namb; j += 128) {
            if (s_amb_ex[j] >= th) {
                int p = atomicAdd(&s_cnt, 1);
                s_idx[p] = s_amb_idx[j];
                s_wv[p] = expf(s_amb_v[j] - m);
            }
        }
        __syncthreads();
    } else {
        // vlen < 64: reference kth = NEG -> keep all entries (masked get weight 0,
        // except vlen==0 where softmax is uniform over all 2048).
        const int keepN = (vlen == 0) ? 2048 : vlen;
        #pragma unroll
        for (int i = 0; i < 16; ++i) {
            int k = tid + (i << 7);
            if (k < keepN) {
                int p = atomicAdd(&s_cnt, 1);
                s_idx[p] = k;
                s_wv[p] = expf(vreg[i] - m);   // vlen==0: exp(0)=1 -> uniform
            }
        }
        __syncthreads();
    }

    // ---- Z and sparse AV ----
    const int nnz = s_cnt;
    float z = 0.f;
    for (int j = tid; j < nnz; j += 128) z += s_wv[j];
    s_red[tid] = z;
    __syncthreads();
    #pragma unroll
    for (int s = 64; s > 0; s >>= 1) {
        if (tid < s) s_red[tid] += s_red[tid + s];
        __syncthreads();
    }
    const float Zinv = 1.0f / s_red[0];

    const float* vb = Vg + ((size_t)b * K_DIM) * D_DIM;
    float a0 = 0.f, a1 = 0.f;
    #pragma unroll 4
    for (int i = 0; i < nnz; ++i) {
        float w = s_wv[i];
        const float* vr = vb + ((size_t)s_idx[i] << 8);
        a0 = fmaf(w, vr[tid], a0);
        a1 = fmaf(w, vr[tid + 128], a1);
    }
    float* o = out + (size_t)rowid * D_DIM;
    o[tid] = a0 * Zinv;
    o[tid + 128] = a1 * Zinv;
}

// ============================ launch ============================

extern "C" void kernel_launch(void* const* d_in, const int* in_sizes, int n_in,
                              void* d_out, int out_size) {
    const float* q  = (const float*)d_in[0];
    const float* k  = (const float*)d_in[1];
    const float* v  = (const float*)d_in[2];
    const int*   vl = (const int*)d_in[3];
    float* out = (float*)d_out;

    cudaFuncSetAttribute(sa_gemm_scores, cudaFuncAttributeMaxDynamicSharedMemorySize, SMEM_BYTES);

    dim3 g1(K_DIM / 128, Q_DIM / 128, B_DIM);   // (16, 16, 8)
    sa_gemm_scores<<<g1, 256, SMEM_BYTES>>>(q, k);
    sa_topk_softmax_av<<<B_DIM * Q_DIM, 128>>>(q, k, v, vl, out);
}

// round 9
// speedup vs baseline: 1.8519x; 1.8519x over previous
#include <cuda_runtime.h>
#include <cuda_bf16.h>
#include <cstdint>
#include <cstddef>

// Problem: B=8, Q=2048, K=2048, D=256, TOP_K=64
#define B_DIM 8
#define Q_DIM 2048
#define K_DIM 2048
#define D_DIM 256
#define NEGV (-1000000.0f)

// 8*2048*2048 fp32 scores scratch (134 MB) — static device global (no allocs allowed).
__device__ float g_scores[(size_t)B_DIM * Q_DIM * K_DIM];

// ============================ helpers ============================

__device__ __forceinline__ uint32_t smem_u32(const void* p) {
    uint32_t a;
    asm("{ .reg .u64 t; cvta.to.shared.u64 t, %1; cvt.u32.u64 %0, t; }" : "=r"(a) : "l"(p));
    return a;
}

__device__ __forceinline__ uint32_t pack_bf2(float a, float b) {
    __nv_bfloat16 ha = __float2bfloat16(a);
    __nv_bfloat16 hb = __float2bfloat16(b);
    return (uint32_t)__bfloat16_as_ushort(ha) | ((uint32_t)__bfloat16_as_ushort(hb) << 16);
}
__device__ __forceinline__ float bf_res(float x) {
    return x - __bfloat162float(__float2bfloat16(x));
}

// ldmatrix.x4 from a SW128-swizzled [rows x 64 bf16] tile (128 bytes/row).
__device__ __forceinline__ void ldsm4(uint32_t sbase, int row, int kbyte, uint32_t r[4]) {
    uint32_t off = (uint32_t)(row << 7) + (uint32_t)kbyte;
    uint32_t sw = off ^ ((off >> 3) & 0x70);
    asm volatile("ldmatrix.sync.aligned.m8n8.x4.shared.b16 {%0,%1,%2,%3}, [%4];"
                 : "=r"(r[0]), "=r"(r[1]), "=r"(r[2]), "=r"(r[3])
                 : "r"(sbase + sw));
}

__device__ __forceinline__ void mma16816(float d[4], const uint32_t a[4],
                                         uint32_t b0, uint32_t b1) {
    asm volatile(
        "mma.sync.aligned.m16n8k16.row.col.f32.bf16.bf16.f32 "
        "{%0,%1,%2,%3}, {%4,%5,%6,%7}, {%8,%9}, {%0,%1,%2,%3};"
        : "+f"(d[0]), "+f"(d[1]), "+f"(d[2]), "+f"(d[3])
        : "r"(a[0]), "r"(a[1]), "r"(a[2]), "r"(a[3]), "r"(b0), "r"(b1));
}

// ============================ Kernel 1: scores = Q·K^T / 16 ============================
// fp32 emulated as 3x bf16 HMMA passes (Ah·Bh + Ah·Bl + Al·Bh). CTA tile 128(M) x 128(N),
// K loop in 4 chunks of 64 floats. 8 warps (4m x 2n), warp tile 32x64, mma.m16n8k16.
// Tiles with n0 >= valid_len[b] are fully masked downstream and never read -> early exit.

#define SM_A_HI 0u
#define SM_A_LO 16384u
#define SM_B_HI 32768u
#define SM_B_LO 49152u
#define SMEM_BYTES 65536

__device__ __forceinline__ void gemm_pass(uint32_t sA, uint32_t sB, int wm, int wn,
                                          int lane, float acc[2][8][4]) {
    const int lrow = lane & 15;
    const int lkb = (lane >> 4) << 4;   // 0 or 16 bytes
    #pragma unroll
    for (int ks = 0; ks < 4; ++ks) {
        const int kbyte = (ks << 5) + lkb;
        uint32_t a[2][4];
        ldsm4(sA, (wm << 5) + lrow, kbyte, a[0]);
        ldsm4(sA, (wm << 5) + 16 + lrow, kbyte, a[1]);
        uint32_t bb[4][4];
        #pragma unroll
        for (int np = 0; np < 4; ++np)
            ldsm4(sB, (wn << 6) + (np << 4) + lrow, kbyte, bb[np]);
        #pragma unroll
        for (int mt = 0; mt < 2; ++mt)
            #pragma unroll
            for (int nt = 0; nt < 8; ++nt)
                mma16816(acc[mt][nt], a[mt], bb[nt >> 1][nt & 1], bb[nt >> 1][2 + (nt & 1)]);
    }
}

__global__ void __launch_bounds__(256, 2)
sa_gemm_scores(const float* __restrict__ Qg, const float* __restrict__ Kg,
               const int* __restrict__ vlens) {
    const int b = blockIdx.z;
    const int n0 = blockIdx.x << 7;
    if (n0 >= vlens[b]) return;   // fully-masked key tile: scores never read

    extern __shared__ char smem[];
    const int tid = threadIdx.x;
    const int wid = tid >> 5;
    const int lane = tid & 31;
    const int wm = wid & 3;
    const int wn = wid >> 2;
    const uint32_t sb = smem_u32(smem);

    const int m0 = blockIdx.y << 7;
    const float* Ag = Qg + ((size_t)(b * Q_DIM + m0)) * D_DIM;
    const float* Bg = Kg + ((size_t)(b * K_DIM + n0)) * D_DIM;

    float acc[2][8][4];
    #pragma unroll
    for (int mt = 0; mt < 2; ++mt)
        #pragma unroll
        for (int nt = 0; nt < 8; ++nt)
            #pragma unroll
            for (int j = 0; j < 4; ++j) acc[mt][nt][j] = 0.f;

    #pragma unroll 1
    for (int c = 0; c < 4; ++c) {
        if (c) __syncthreads();

        #pragma unroll
        for (int t = 0; t < 8; ++t) {
            int idx = tid + (t << 8);
            int row = idx >> 4;
            int c4  = (idx & 15) << 2;
            size_t go = (size_t)row * D_DIM + (c << 6) + c4;
            float4 va = *(const float4*)(Ag + go);
            float4 vb = *(const float4*)(Bg + go);
            uint32_t off = (uint32_t)(row << 7) + (uint32_t)(c4 << 1);
            uint32_t sw = off ^ ((off >> 3) & 0x70);

            *(uint32_t*)(smem + SM_A_HI + sw)     = pack_bf2(va.x, va.y);
            *(uint32_t*)(smem + SM_A_HI + sw + 4) = pack_bf2(va.z, va.w);
            *(uint32_t*)(smem + SM_A_LO + sw)     = pack_bf2(bf_res(va.x), bf_res(va.y));
            *(uint32_t*)(smem + SM_A_LO + sw + 4) = pack_bf2(bf_res(va.z), bf_res(va.w));

            *(uint32_t*)(smem + SM_B_HI + sw)     = pack_bf2(vb.x, vb.y);
            *(uint32_t*)(smem + SM_B_HI + sw + 4) = pack_bf2(vb.z, vb.w);
            *(uint32_t*)(smem + SM_B_LO + sw)     = pack_bf2(bf_res(vb.x), bf_res(vb.y));
            *(uint32_t*)(smem + SM_B_LO + sw + 4) = pack_bf2(bf_res(vb.z), bf_res(vb.w));
        }
        __syncthreads();

        gemm_pass(sb + SM_A_HI, sb + SM_B_HI, wm, wn, lane, acc);  // hi*hi
        gemm_pass(sb + SM_A_HI, sb + SM_B_LO, wm, wn, lane, acc);  // hi*lo
        gemm_pass(sb + SM_A_LO, sb + SM_B_HI, wm, wn, lane, acc);  // lo*hi
    }

    float* gout = g_scores + ((size_t)(b * Q_DIM + m0)) * K_DIM + n0;
    const int rb = (wm << 5) + (lane >> 2);
    const int cb = (wn << 6) + ((lane & 3) << 1);
    #pragma unroll
    for (int mt = 0; mt < 2; ++mt)
        #pragma unroll
        for (int nt = 0; nt < 8; ++nt) {
            int r = rb + (mt << 4);
            int cc = cb + (nt << 3);
            float2 v0 = make_float2(acc[mt][nt][0] * 0.0625f, acc[mt][nt][1] * 0.0625f);
            float2 v1 = make_float2(acc[mt][nt][2] * 0.0625f, acc[mt][nt][3] * 0.0625f);
            *(float2*)&gout[(size_t)r * K_DIM + cc] = v0;
            *(float2*)&gout[(size_t)(r + 8) * K_DIM + cc] = v1;
        }
}

// ============================ Kernel 2 ============================
// Per (b,q) row: masked load -> approx 64th threshold (3-round radix on top-24 bits,
// per-warp privatized histograms, warp-0 shfl digit scan) -> exact fp32 recompute of
// boundary-ambiguous entries -> reference-exact selection (>= kth, ties kept) ->
// softmax -> warp-cooperative compacted sparse AV.

__device__ __forceinline__ unsigned f2srt(float f) {
    unsigned u = __float_as_uint(f);
    return (u & 0x80000000u) ? ~u : (u | 0x80000000u);
}
__device__ __forceinline__ float srt2f(unsigned s) {
    unsigned u = (s & 0x80000000u) ? (s & 0x7FFFFFFFu) : ~s;
    return __uint_as_float(u);
}

#define AMB_CAP 96
#define CAP 160
#define BAND_LO 1.0e-3f
#define BAND_HI 1.2e-3f   // 1e-3 + radix 8-bit truncation margin (<=1.5e-4)

__global__ void __launch_bounds__(128)
sa_topk_softmax_av(const float* __restrict__ Qg, const float* __restrict__ Kg,
                   const float* __restrict__ Vg, const int* __restrict__ vlens,
                   float* __restrict__ out) {
    __shared__ float s_qf[256];
    __shared__ union {
        unsigned hist[4][256];
        float    part[4][256];
    } s_u;
    __shared__ float    s_red[4];
    __shared__ int      s_idx[CAP];
    __shared__ float    s_wv[CAP];
    __shared__ int      s_amb_idx[AMB_CAP];
    __shared__ float    s_amb_v[AMB_CAP];
    __shared__ float    s_amb_ex[AMB_CAP];
    __shared__ unsigned s_pref;
    __shared__ int      s_r;
    __shared__ int      s_cnt;
    __shared__ int      s_namb;
    __shared__ float    s_thex;

    const int tid = threadIdx.x;
    const int lane = tid & 31;
    const int wrp = tid >> 5;
    const int rowid = blockIdx.x;          // b*2048 + q
    const int b = rowid >> 11;
    const int vlen = vlens[b];
    const float* sc = g_scores + (size_t)rowid * K_DIM;
    const float* qrow = Qg + (size_t)rowid * D_DIM;

    // Stage Q row (for exact boundary recompute).
    s_qf[tid] = qrow[tid];
    s_qf[tid + 128] = qrow[tid + 128];

    // Masked score load — predicated so the skipped g_scores region is never read.
    float vreg[16];
    float lmax = NEGV;
    #pragma unroll
    for (int i = 0; i < 16; ++i) {
        int k = tid + (i << 7);
        float v = (k < vlen) ? sc[k] : NEGV;
        vreg[i] = v;
        lmax = fmaxf(lmax, v);
    }
    // Row max: warp shfl + tiny smem combine.
    #pragma unroll
    for (int o = 16; o > 0; o >>= 1) lmax = fmaxf(lmax, __shfl_xor_sync(0xFFFFFFFFu, lmax, o));
    if (lane == 0) s_red[wrp] = lmax;
    if (tid == 0) { s_cnt = 0; s_namb = 0; s_pref = 0u; s_r = 64; }
    __syncthreads();
    const float m = fmaxf(fmaxf(s_red[0], s_red[1]), fmaxf(s_red[2], s_red[3]));

    if (vlen >= 64) {
        // ---- approx kth: 3-round MSB radix select (top 24 bits), valid entries only ----
        unsigned prefmask = 0u;
        #pragma unroll 1
        for (int shift = 24; shift >= 8; shift -= 8) {
            #pragma unroll
            for (int j = 0; j < 8; ++j) ((unsigned*)s_u.hist)[tid + (j << 7)] = 0u;
            __syncthreads();
            const unsigned pref = s_pref;
            #pragma unroll
            for (int i = 0; i < 16; ++i) {
                int k = tid + (i << 7);
                if (k < vlen) {
                    unsigned u = f2srt(vreg[i]);
                    if ((u & prefmask) == pref)
                        atomicAdd(&s_u.hist[wrp][(u >> shift) & 255], 1u);
                }
            }
            __syncthreads();
            if (wrp == 0) {
                const int r = s_r;
                const int hi = 255 - (lane << 3);   // lane's 8-bin chunk, descending
                unsigned hloc[8];
                unsigned cs = 0;
                #pragma unroll
                for (int j = 0; j < 8; ++j) {
                    int bin = hi - j;
                    unsigned h = s_u.hist[0][bin] + s_u.hist[1][bin] +
                                 s_u.hist[2][bin] + s_u.hist[3][bin];
                    hloc[j] = h;
                    cs += h;
                }
                unsigned pre = cs;   // inclusive scan over lanes (descending-bin order)
                #pragma unroll
                for (int o = 1; o < 32; o <<= 1) {
                    unsigned t = __shfl_up_sync(0xFFFFFFFFu, pre, o);
                    if (lane >= o) pre += t;
                }
                unsigned before = pre - cs;
                if (before < (unsigned)r && (unsigned)r <= pre) {
                    unsigned acc = before;
                    #pragma unroll
                    for (int j = 0; j < 8; ++j) {
                        if (acc + hloc[j] >= (unsigned)r) {
                            s_pref |= ((unsigned)(hi - j)) << shift;
                            s_r = r - (int)acc;
                            break;
                        }
                        acc += hloc[j];
                    }
                }
            }
            __syncthreads();
            prefmask |= 0xFFu << shift;
        }
        const float t = srt2f(s_pref);   // lower 8 bits zero: t <= kth_approx <= t + ~1.5e-4

        // ---- classify: certain-in (push) / ambiguous (collect) ----
        #pragma unroll
        for (int i = 0; i < 16; ++i) {
            float v = vreg[i];
            if (v > t + BAND_HI) {
                int p = atomicAdd(&s_cnt, 1);
                s_idx[p] = tid + (i << 7);
                s_wv[p] = expf(v - m);
            } else if (v >= t - BAND_LO) {
                int p = atomicAdd(&s_namb, 1);
                if (p < AMB_CAP) {
                    s_amb_idx[p] = tid + (i << 7);
                    s_amb_v[p] = v;
                }
            }
        }
        __syncthreads();
        const int c_in = s_cnt;
        const int namb = min(s_namb, AMB_CAP);

        // ---- exact fp32 scores for ambiguous entries (one warp per entry) ----
        for (int j = wrp; j < namb; j += 4) {
            const float* kr = Kg + ((size_t)(b * K_DIM + s_amb_idx[j])) * D_DIM;
            float4 k0 = *(const float4*)(kr + lane * 4);
            float4 k1 = *(const float4*)(kr + 128 + lane * 4);
            float4 q0 = *(const float4*)(s_qf + lane * 4);
            float4 q1 = *(const float4*)(s_qf + 128 + lane * 4);
            float s = q0.x * k0.x;
            s = fmaf(q0.y, k0.y, s); s = fmaf(q0.z, k0.z, s); s = fmaf(q0.w, k0.w, s);
            s = fmaf(q1.x, k1.x, s); s = fmaf(q1.y, k1.y, s);
            s = fmaf(q1.z, k1.z, s); s = fmaf(q1.w, k1.w, s);
            #pragma unroll
            for (int o = 16; o > 0; o >>= 1) s += __shfl_xor_sync(0xFFFFFFFFu, s, o);
            if (lane == 0) s_amb_ex[j] = s * 0.0625f;
        }
        __syncthreads();

        // ---- exact (64 - c_in)-th largest among ambiguous; reference tie semantics ----
        if (tid == 0) {
            int need = 64 - c_in;   // >= 1
            float th = s_amb_ex[0];
            for (int j = 0; j < namb; ++j) {
                float x = s_amb_ex[j];
                int gt = 0, ge = 0;
                for (int l = 0; l < namb; ++l) {
                    gt += (s_amb_ex[l] > x);
                    ge += (s_amb_ex[l] >= x);
                }
                if (gt < need && ge >= need) { th = x; break; }
            }
            s_thex = th;
        }
        __syncthreads();
        const float th = s_thex;
        for (int j = tid; j < namb; j += 128) {
            if (s_amb_ex[j] >= th) {
                int p = atomicAdd(&s_cnt, 1);
                s_idx[p] = s_amb_idx[j];
                s_wv[p] = expf(s_amb_v[j] - m);
            }
        }
        __syncthreads();
    } else if (vlen > 0) {
        // vlen in [1,64): reference kth = NEG -> keep all valid (masked weights = 0 exactly).
        #pragma unroll
        for (int i = 0; i < 16; ++i) {
            int k = tid + (i << 7);
            if (k < vlen) { s_idx[k] = k; s_wv[k] = expf(vreg[i] - m); }
        }
        if (tid == 0) s_cnt = vlen;
        __syncthreads();
    }
    // vlen == 0: uniform 1/2048 over all keys — handled below (s_cnt stays 0).

    // ---- Z ----
    const int nnz = s_cnt;
    float Zinv;
    if (vlen == 0) {
        Zinv = 1.0f / 2048.0f;
    } else {
        float z = 0.f;
        for (int j = tid; j < nnz; j += 128) z += s_wv[j];
        #pragma unroll
        for (int o = 16; o > 0; o >>= 1) z += __shfl_xor_sync(0xFFFFFFFFu, z, o);
        __syncthreads();   // s_red reuse
        if (lane == 0) s_red[wrp] = z;
        __syncthreads();
        Zinv = 1.0f / (s_red[0] + s_red[1] + s_red[2] + s_red[3]);
    }

    // ---- warp-cooperative AV: warp w handles entries w, w+4, ...; lane owns 8 dims ----
    const float* vb = Vg + ((size_t)b * K_DIM) * D_DIM;
    float4 acc0 = make_float4(0.f, 0.f, 0.f, 0.f);
    float4 acc1 = make_float4(0.f, 0.f, 0.f, 0.f);
    const int l4 = lane << 2;

    if (vlen == 0) {
        // uniform: sum all 2048 V rows (weight 1 each)
        for (int i = wrp; i < 2048; i += 4) {
            const float* vr = vb + ((size_t)i << 8);
            float4 v0 = *(const float4*)(vr + l4);
            float4 v1 = *(const float4*)(vr + 128 + l4);
            acc0.x += v0.x; acc0.y += v0.y; acc0.z += v0.z; acc0.w += v0.w;
            acc1.x += v1.x; acc1.y += v1.y; acc1.z += v1.z; acc1.w += v1.w;
        }
    } else {
        int i = wrp;
        for (; i + 4 < nnz; i += 8) {   // unroll x2 for MLP
            float w0 = s_wv[i];       const float* vr0 = vb + ((size_t)s_idx[i] << 8);
            float w1 = s_wv[i + 4];   const float* vr1 = vb + ((size_t)s_idx[i + 4] << 8);
            float4 a0 = *(const float4*)(vr0 + l4);
            float4 a1 = *(const float4*)(vr0 + 128 + l4);
            float4 b0 = *(const float4*)(vr1 + l4);
            float4 b1 = *(const float4*)(vr1 + 128 + l4);
            acc0.x = fmaf(w0, a0.x, acc0.x); acc0.y = fmaf(w0, a0.y, acc0.y);
            acc0.z = fmaf(w0, a0.z, acc0.z); acc0.w = fmaf(w0, a0.w, acc0.w);
            acc1.x = fmaf(w0, a1.x, acc1.x); acc1.y = fmaf(w0, a1.y, acc1.y);
            acc1.z = fmaf(w0, a1.z, acc1.z); acc1.w = fmaf(w0, a1.w, acc1.w);
            acc0.x = fmaf(w1, b0.x, acc0.x); acc0.y = fmaf(w1, b0.y, acc0.y);
            acc0.z = fmaf(w1, b0.z, acc0.z); acc0.w = fmaf(w1, b0.w, acc0.w);
            acc1.x = fmaf(w1, b1.x, acc1.x); acc1.y = fmaf(w1, b1.y, acc1.y);
            acc1.z = fmaf(w1, b1.z, acc1.z); acc1.w = fmaf(w1, b1.w, acc1.w);
        }
        for (; i < nnz; i += 4) {
            float w = s_wv[i];
            const float* vr = vb + ((size_t)s_idx[i] << 8);
            float4 a0 = *(const float4*)(vr + l4);
            float4 a1 = *(const float4*)(vr + 128 + l4);
            acc0.x = fmaf(w, a0.x, acc0.x); acc0.y = fmaf(w, a0.y, acc0.y);
            acc0.z = fmaf(w, a0.z, acc0.z); acc0.w = fmaf(w, a0.w, acc0.w);
            acc1.x = fmaf(w, a1.x, acc1.x); acc1.y = fmaf(w, a1.y, acc1.y);
            acc1.z = fmaf(w, a1.z, acc1.z); acc1.w = fmaf(w, a1.w, acc1.w);
        }
    }
    __syncthreads();   // s_u reuse (hist -> part)
    *(float4*)&s_u.part[wrp][l4] = acc0;
    *(float4*)&s_u.part[wrp][128 + l4] = acc1;
    __syncthreads();

    float* o = out + (size_t)rowid * D_DIM;
    float r0 = s_u.part[0][tid] + s_u.part[1][tid] + s_u.part[2][tid] + s_u.part[3][tid];
    float r1 = s_u.part[0][tid + 128] + s_u.part[1][tid + 128] +
               s_u.part[2][tid + 128] + s_u.part[3][tid + 128];
    o[tid] = r0 * Zinv;
    o[tid + 128] = r1 * Zinv;
}

// ============================ launch ============================

extern "C" void kernel_launch(void* const* d_in, const int* in_sizes, int n_in,
                              void* d_out, int out_size) {
    const float* q  = (const float*)d_in[0];
    const float* k  = (const float*)d_in[1];
    const float* v  = (const float*)d_in[2];
    const int*   vl = (const int*)d_in[3];
    float* out = (float*)d_out;

    cudaFuncSetAttribute(sa_gemm_scores, cudaFuncAttributeMaxDynamicSharedMemorySize, SMEM_BYTES);

    dim3 g1(K_DIM / 128, Q_DIM / 128, B_DIM);   // (16, 16, 8)
    sa_gemm_scores<<<g1, 256, SMEM_BYTES>>>(q, k, vl);
    sa_topk_softmax_av<<<B_DIM * Q_DIM, 128>>>(q, k, v, vl, out);
}

// round 11
// speedup vs baseline: 2.1566x; 1.1645x over previous
#include <cuda_runtime.h>
#include <cuda_bf16.h>
#include <cstdint>
#include <cstddef>

// Problem: B=8, Q=2048, K=2048, D=256, TOP_K=64
#define B_DIM 8
#define Q_DIM 2048
#define K_DIM 2048
#define D_DIM 256
#define NEGV (-1000000.0f)

// Static device scratch (no allocs allowed).
__device__ float g_scores[(size_t)B_DIM * Q_DIM * K_DIM];           // 134 MB
#define QK_ELEMS ((size_t)B_DIM * 2048 * 256)
__device__ __nv_bfloat16 g_qhi[QK_ELEMS];                            // 8 MB each
__device__ __nv_bfloat16 g_qlo[QK_ELEMS];
__device__ __nv_bfloat16 g_khi[QK_ELEMS];
__device__ __nv_bfloat16 g_klo[QK_ELEMS];

// ============================ helpers ============================

__device__ __forceinline__ uint32_t smem_u32(const void* p) {
    uint32_t a;
    asm("{ .reg .u64 t; cvta.to.shared.u64 t, %1; cvt.u32.u64 %0, t; }" : "=r"(a) : "l"(p));
    return a;
}

__device__ __forceinline__ uint32_t pack_bf2(float a, float b) {
    __nv_bfloat16 ha = __float2bfloat16(a);
    __nv_bfloat16 hb = __float2bfloat16(b);
    return (uint32_t)__bfloat16_as_ushort(ha) | ((uint32_t)__bfloat16_as_ushort(hb) << 16);
}
__device__ __forceinline__ float bf_res(float x) {
    return x - __bfloat162float(__float2bfloat16(x));
}

__device__ __forceinline__ void cp16(uint32_t dst, const void* src) {
    asm volatile("cp.async.cg.shared.global [%0], [%1], 16;" :: "r"(dst), "l"(src));
}
#define CP_COMMIT() asm volatile("cp.async.commit_group;" ::: "memory")

// ldmatrix.x4 from a SW128-swizzled [rows x 64 bf16] tile (128 bytes/row).
__device__ __forceinline__ void ldsm4(uint32_t sbase, int row, int kbyte, uint32_t r[4]) {
    uint32_t off = (uint32_t)(row << 7) + (uint32_t)kbyte;
    uint32_t sw = off ^ ((off >> 3) & 0x70);
    asm volatile("ldmatrix.sync.aligned.m8n8.x4.shared.b16 {%0,%1,%2,%3}, [%4];"
                 : "=r"(r[0]), "=r"(r[1]), "=r"(r[2]), "=r"(r[3])
                 : "r"(sbase + sw));
}

__device__ __forceinline__ void mma16816(float d[4], const uint32_t a[4],
                                         uint32_t b0, uint32_t b1) {
    asm volatile(
        "mma.sync.aligned.m16n8k16.row.col.f32.bf16.bf16.f32 "
        "{%0,%1,%2,%3}, {%4,%5,%6,%7}, {%8,%9}, {%0,%1,%2,%3};"
        : "+f"(d[0]), "+f"(d[1]), "+f"(d[2]), "+f"(d[3])
        : "r"(a[0]), "r"(a[1]), "r"(a[2]), "r"(a[3]), "r"(b0), "r"(b1));
}

// ============================ Kernel 0: pre-split Q/K into bf16 hi/lo ============================

__global__ void __launch_bounds__(256)
sa_preconvert(const float* __restrict__ Qg, const float* __restrict__ Kg) {
    size_t i = (size_t)blockIdx.x * 256 + threadIdx.x;   // float4 index
    float4 q = ((const float4*)Qg)[i];
    float4 k = ((const float4*)Kg)[i];
    ((uint2*)g_qhi)[i] = make_uint2(pack_bf2(q.x, q.y), pack_bf2(q.z, q.w));
    ((uint2*)g_qlo)[i] = make_uint2(pack_bf2(bf_res(q.x), bf_res(q.y)),
                                    pack_bf2(bf_res(q.z), bf_res(q.w)));
    ((uint2*)g_khi)[i] = make_uint2(pack_bf2(k.x, k.y), pack_bf2(k.z, k.w));
    ((uint2*)g_klo)[i] = make_uint2(pack_bf2(bf_res(k.x), bf_res(k.y)),
                                    pack_bf2(bf_res(k.z), bf_res(k.w)));
}

// ============================ Kernel 1: scores = Q·K^T / 16 ============================
// fp32 via 3 bf16 HMMA terms (Ah·Bh + Ah·Bl + Al·Bh); Ah fragments shared across the
// two B planes. CTA tile 128x128, K in 4 chunks of 64. cp.async 2-stage double buffer
// (4 tiles x 16KB = 64KB/stage, 128KB total, 1 CTA/SM). Masked key tiles skipped.

#define STAGE_BYTES 65536
#define SMEM_BYTES  (2 * STAGE_BYTES)
// within-stage tile offsets: A_hi +0, A_lo +16K, B_hi +32K, B_lo +48K

__device__ __forceinline__ void issue_stage(uint32_t sstage,
                                            const __nv_bfloat16* qh,
                                            const __nv_bfloat16* ql,
                                            const __nv_bfloat16* kh,
                                            const __nv_bfloat16* kl,
                                            int tid, int c) {
    #pragma unroll
    for (int j = 0; j < 16; ++j) {
        int g = tid + (j << 8);          // 0..4095 granules of 16B
        int tile = g >> 10;              // 0:A_hi 1:A_lo 2:B_hi 3:B_lo (warp-uniform)
        int t = g & 1023;
        int row = t >> 3;
        int gc = t & 7;
        const __nv_bfloat16* src = (tile == 0) ? qh : (tile == 1) ? ql
                                 : (tile == 2) ? kh : kl;
        const __nv_bfloat16* s = src + (size_t)row * D_DIM + (c << 6) + (gc << 3);
        uint32_t off = (uint32_t)(row << 7) + (uint32_t)(gc << 4);
        uint32_t sw = off ^ ((off >> 3) & 0x70);
        cp16(sstage + (uint32_t)(tile << 14) + sw, s);
    }
}

__global__ void __launch_bounds__(256, 1)
sa_gemm_scores(const int* __restrict__ vlens) {
    const int b = blockIdx.z;
    const int n0 = blockIdx.x << 7;
    if (n0 >= vlens[b]) return;   // fully-masked key tile: scores never read

    extern __shared__ char smem[];
    const int tid = threadIdx.x;
    const int wid = tid >> 5;
    const int lane = tid & 31;
    const int wm = wid & 3;
    const int wn = wid >> 2;
    const uint32_t sb = smem_u32(smem);

    const int m0 = blockIdx.y << 7;
    const __nv_bfloat16* qh = g_qhi + (size_t)(b * Q_DIM + m0) * D_DIM;
    const __nv_bfloat16* ql = g_qlo + (size_t)(b * Q_DIM + m0) * D_DIM;
    const __nv_bfloat16* kh = g_khi + (size_t)(b * K_DIM + n0) * D_DIM;
    const __nv_bfloat16* kl = g_klo + (size_t)(b * K_DIM + n0) * D_DIM;

    float acc[2][8][4];
    #pragma unroll
    for (int mt = 0; mt < 2; ++mt)
        #pragma unroll
        for (int nt = 0; nt < 8; ++nt)
            #pragma unroll
            for (int j = 0; j < 4; ++j) acc[mt][nt][j] = 0.f;

    issue_stage(sb, qh, ql, kh, kl, tid, 0);
    CP_COMMIT();

    const int lrow = lane & 15;
    const int lkb = (lane >> 4) << 4;

    #pragma unroll 1
    for (int c = 0; c < 4; ++c) {
        if (c < 3) {
            issue_stage(sb + (uint32_t)(((c + 1) & 1) * STAGE_BYTES), qh, ql, kh, kl, tid, c + 1);
            CP_COMMIT();
            asm volatile("cp.async.wait_group 1;" ::: "memory");
        } else {
            asm volatile("cp.async.wait_group 0;" ::: "memory");
        }
        __syncthreads();

        const uint32_t sA_hi = sb + (uint32_t)((c & 1) * STAGE_BYTES);
        const uint32_t sA_lo = sA_hi + 16384u;
        const uint32_t sB_hi = sA_hi + 32768u;
        const uint32_t sB_lo = sA_hi + 49152u;

        // Pass A: Ah·Bh + Ah·Bl (shares Ah fragments across both B planes).
        #pragma unroll
        for (int ks = 0; ks < 4; ++ks) {
            const int kbyte = (ks << 5) + lkb;
            uint32_t ah[2][4];
            ldsm4(sA_hi, (wm << 5) + lrow, kbyte, ah[0]);
            ldsm4(sA_hi, (wm << 5) + 16 + lrow, kbyte, ah[1]);
            uint32_t bh[4][4];
            #pragma unroll
            for (int np = 0; np < 4; ++np)
                ldsm4(sB_hi, (wn << 6) + (np << 4) + lrow, kbyte, bh[np]);
            #pragma unroll
            for (int mt = 0; mt < 2; ++mt)
                #pragma unroll
                for (int nt = 0; nt < 8; ++nt)
                    mma16816(acc[mt][nt], ah[mt], bh[nt >> 1][nt & 1], bh[nt >> 1][2 + (nt & 1)]);
            uint32_t bl[4][4];
            #pragma unroll
            for (int np = 0; np < 4; ++np)
                ldsm4(sB_lo, (wn << 6) + (np << 4) + lrow, kbyte, bl[np]);
            #pragma unroll
            for (int mt = 0; mt < 2; ++mt)
                #pragma unroll
                for (int nt = 0; nt < 8; ++nt)
                    mma16816(acc[mt][nt], ah[mt], bl[nt >> 1][nt & 1], bl[nt >> 1][2 + (nt & 1)]);
        }
        // Pass B: Al·Bh.
        #pragma unroll
        for (int ks = 0; ks < 4; ++ks) {
            const int kbyte = (ks << 5) + lkb;
            uint32_t al[2][4];
            ldsm4(sA_lo, (wm << 5) + lrow, kbyte, al[0]);
            ldsm4(sA_lo, (wm << 5) + 16 + lrow, kbyte, al[1]);
            uint32_t bh[4][4];
            #pragma unroll
            for (int np = 0; np < 4; ++np)
                ldsm4(sB_hi, (wn << 6) + (np << 4) + lrow, kbyte, bh[np]);
            #pragma unroll
            for (int mt = 0; mt < 2; ++mt)
                #pragma unroll
                for (int nt = 0; nt < 8; ++nt)
                    mma16816(acc[mt][nt], al[mt], bh[nt >> 1][nt & 1], bh[nt >> 1][2 + (nt & 1)]);
        }
        __syncthreads();
    }

    float* gout = g_scores + ((size_t)(b * Q_DIM + m0)) * K_DIM + n0;
    const int rb = (wm << 5) + (lane >> 2);
    const int cb = (wn << 6) + ((lane & 3) << 1);
    #pragma unroll
    for (int mt = 0; mt < 2; ++mt)
        #pragma unroll
        for (int nt = 0; nt < 8; ++nt) {
            int r = rb + (mt << 4);
            int cc = cb + (nt << 3);
            float2 v0 = make_float2(acc[mt][nt][0] * 0.0625f, acc[mt][nt][1] * 0.0625f);
            float2 v1 = make_float2(acc[mt][nt][2] * 0.0625f, acc[mt][nt][3] * 0.0625f);
            *(float2*)&gout[(size_t)r * K_DIM + cc] = v0;
            *(float2*)&gout[(size_t)(r + 8) * K_DIM + cc] = v1;
        }
}

// ============================ Kernel 2 ============================
// Per (b,q) row: masked load -> approx 64th threshold (2-round radix, top-16 bits,
// bin bounds handled exactly via t_lo/t_hi) -> exact fp32 recompute of boundary
// entries -> reference-exact selection (>= kth, ties kept) -> softmax -> AV gather.

__device__ __forceinline__ unsigned f2srt(float f) {
    unsigned u = __float_as_uint(f);
    return (u & 0x80000000u) ? ~u : (u | 0x80000000u);
}
__device__ __forceinline__ float srt2f(unsigned s) {
    unsigned u = (s & 0x80000000u) ? (s & 0x7FFFFFFFu) : ~s;
    return __uint_as_float(u);
}

#define AMB_CAP 96
#define CAP 160
#define BAND 1.5e-3f   // ~50 sigma of 3-term bf16-split score error (sigma ~= 3e-5)

__global__ void __launch_bounds__(128, 6)
sa_topk_softmax_av(const float* __restrict__ Qg, const float* __restrict__ Kg,
                   const float* __restrict__ Vg, const int* __restrict__ vlens,
                   float* __restrict__ out) {
    __shared__ float s_qf[256];
    __shared__ union {
        unsigned hist[4][256];
        float    part[4][256];
    } s_u;
    __shared__ float    s_red[4];
    __shared__ int      s_idx[CAP];
    __shared__ float    s_wv[CAP];
    __shared__ int      s_amb_idx[AMB_CAP];
    __shared__ float    s_amb_v[AMB_CAP];
    __shared__ float    s_amb_ex[AMB_CAP];
    __shared__ unsigned s_pref;
    __shared__ int      s_r;
    __shared__ int      s_cnt;
    __shared__ int      s_namb;
    __shared__ float    s_thex;

    const int tid = threadIdx.x;
    const int lane = tid & 31;
    const int wrp = tid >> 5;
    const int rowid = blockIdx.x;          // b*2048 + q
    const int b = rowid >> 11;
    const int vlen = vlens[b];
    const float* sc = g_scores + (size_t)rowid * K_DIM;
    const float* qrow = Qg + (size_t)rowid * D_DIM;

    s_qf[tid] = qrow[tid];
    s_qf[tid + 128] = qrow[tid + 128];

    float vreg[16];
    float lmax = NEGV;
    #pragma unroll
    for (int i = 0; i < 16; ++i) {
        int k = tid + (i << 7);
        float v = (k < vlen) ? sc[k] : NEGV;
        vreg[i] = v;
        lmax = fmaxf(lmax, v);
    }
    #pragma unroll
    for (int o = 16; o > 0; o >>= 1) lmax = fmaxf(lmax, __shfl_xor_sync(0xFFFFFFFFu, lmax, o));
    if (lane == 0) s_red[wrp] = lmax;
    if (tid == 0) { s_cnt = 0; s_namb = 0; s_pref = 0u; s_r = 64; }
    __syncthreads();
    const float m = fmaxf(fmaxf(s_red[0], s_red[1]), fmaxf(s_red[2], s_red[3]));

    if (vlen >= 64) {
        // ---- approx kth: 2-round MSB radix select (top 16 bits), valid entries only ----
        unsigned prefmask = 0u;
        #pragma unroll 1
        for (int shift = 24; shift >= 16; shift -= 8) {
            #pragma unroll
            for (int j = 0; j < 8; ++j) ((unsigned*)s_u.hist)[tid + (j << 7)] = 0u;
            __syncthreads();
            const unsigned pref = s_pref;
            #pragma unroll
            for (int i = 0; i < 16; ++i) {
                int k = tid + (i << 7);
                if (k < vlen) {
                    unsigned u = f2srt(vreg[i]);
                    if ((u & prefmask) == pref)
                        atomicAdd(&s_u.hist[wrp][(u >> shift) & 255], 1u);
                }
            }
            __syncthreads();
            if (wrp == 0) {
                const int r = s_r;
                const int hi = 255 - (lane << 3);
                unsigned hloc[8];
                unsigned cs = 0;
                #pragma unroll
                for (int j = 0; j < 8; ++j) {
                    int bin = hi - j;
                    unsigned h = s_u.hist[0][bin] + s_u.hist[1][bin] +
                                 s_u.hist[2][bin] + s_u.hist[3][bin];
                    hloc[j] = h;
                    cs += h;
                }
                unsigned pre = cs;
                #pragma unroll
                for (int o = 1; o < 32; o <<= 1) {
                    unsigned t = __shfl_up_sync(0xFFFFFFFFu, pre, o);
                    if (lane >= o) pre += t;
                }
                unsigned before = pre - cs;
                if (before < (unsigned)r && (unsigned)r <= pre) {
                    unsigned acc = before;
                    #pragma unroll
                    for (int j = 0; j < 8; ++j) {
                        if (acc + hloc[j] >= (unsigned)r) {
                            s_pref |= ((unsigned)(hi - j)) << shift;
                            s_r = r - (int)acc;
                            break;
                        }
                        acc += hloc[j];
                    }
                }
            }
            __syncthreads();
            prefmask |= 0xFFu << shift;
        }
        const float t_lo = srt2f(s_pref);            // bin lower edge (<= approx kth)
        const float t_hi = srt2f(s_pref | 0xFFFFu);  // bin upper edge (>= approx kth)

        // ---- classify ----
        #pragma unroll
        for (int i = 0; i < 16; ++i) {
            float v = vreg[i];
            if (v > t_hi + BAND) {
                int p = atomicAdd(&s_cnt, 1);
                s_idx[p] = tid + (i << 7);
                s_wv[p] = expf(v - m);
            } else if (v >= t_lo - BAND) {
                int p = atomicAdd(&s_namb, 1);
                if (p < AMB_CAP) {
                    s_amb_idx[p] = tid + (i << 7);
                    s_amb_v[p] = v;
                }
            }
        }
        __syncthreads();
        const int c_in = s_cnt;
        const int namb = min(s_namb, AMB_CAP);

        // ---- exact fp32 scores for ambiguous entries (one warp per entry) ----
        for (int j = wrp; j < namb; j += 4) {
            const float* kr = Kg + ((size_t)(b * K_DIM + s_amb_idx[j])) * D_DIM;
            float4 k0 = *(const float4*)(kr + lane * 4);
            float4 k1 = *(const float4*)(kr + 128 + lane * 4);
            float4 q0 = *(const float4*)(s_qf + lane * 4);
            float4 q1 = *(const float4*)(s_qf + 128 + lane * 4);
            float s = q0.x * k0.x;
            s = fmaf(q0.y, k0.y, s); s = fmaf(q0.z, k0.z, s); s = fmaf(q0.w, k0.w, s);
            s = fmaf(q1.x, k1.x, s); s = fmaf(q1.y, k1.y, s);
            s = fmaf(q1.z, k1.z, s); s = fmaf(q1.w, k1.w, s);
            #pragma unroll
            for (int o = 16; o > 0; o >>= 1) s += __shfl_xor_sync(0xFFFFFFFFu, s, o);
            if (lane == 0) s_amb_ex[j] = s * 0.0625f;
        }
        __syncthreads();

        // ---- exact (64 - c_in)-th largest among ambiguous; reference tie semantics ----
        if (tid == 0) {
            int need = 64 - c_in;   // >= 1
            float th = s_amb_ex[0];
            for (int j = 0; j < namb; ++j) {
                float x = s_amb_ex[j];
                int gt = 0, ge = 0;
                for (int l = 0; l < namb; ++l) {
                    gt += (s_amb_ex[l] > x);
                    ge += (s_amb_ex[l] >= x);
                }
                if (gt < need && ge >= need) { th = x; break; }
            }
            s_thex = th;
        }
        __syncthreads();
        const float th = s_thex;
        for (int j = tid; j < namb; j += 128) {
            if (s_amb_ex[j] >= th) {
                int p = atomicAdd(&s_cnt, 1);
                s_idx[p] = s_amb_idx[j];
                s_wv[p] = expf(s_amb_v[j] - m);
            }
        }
        __syncthreads();
    } else if (vlen > 0) {
        // vlen in [1,64): reference kth = NEG -> keep all valid (masked weights = 0).
        #pragma unroll
        for (int i = 0; i < 16; ++i) {
            int k = tid + (i << 7);
            if (k < vlen) { s_idx[k] = k; s_wv[k] = expf(vreg[i] - m); }
        }
        if (tid == 0) s_cnt = vlen;
        __syncthreads();
    }
    // vlen == 0: uniform 1/2048 over all keys (s_cnt stays 0).

    // ---- Z ----
    const int nnz = s_cnt;
    float Zinv;
    if (vlen == 0) {
        Zinv = 1.0f / 2048.0f;
    } else {
        float z = 0.f;
        for (int j = tid; j < nnz; j += 128) z += s_wv[j];
        #pragma unroll
        for (int o = 16; o > 0; o >>= 1) z += __shfl_xor_sync(0xFFFFFFFFu, z, o);
        __syncthreads();
        if (lane == 0) s_red[wrp] = z;
        __syncthreads();
        Zinv = 1.0f / (s_red[0] + s_red[1] + s_red[2] + s_red[3]);
    }

    // ---- warp-cooperative AV, unroll x4 for MLP ----
    const float* vb = Vg + ((size_t)b * K_DIM) * D_DIM;
    float4 acc0 = make_float4(0.f, 0.f, 0.f, 0.f);
    float4 acc1 = make_float4(0.f, 0.f, 0.f, 0.f);
    const int l4 = lane << 2;

    if (vlen == 0) {
        for (int i = wrp; i < 2048; i += 4) {
            const float* vr = vb + ((size_t)i << 8);
            float4 v0 = *(const float4*)(vr + l4);
            float4 v1 = *(const float4*)(vr + 128 + l4);
            acc0.x += v0.x; acc0.y += v0.y; acc0.z += v0.z; acc0.w += v0.w;
            acc1.x += v1.x; acc1.y += v1.y; acc1.z += v1.z; acc1.w += v1.w;
        }
    } else {
        int i = wrp;
        for (; i + 12 < nnz; i += 16) {
            float w0 = s_wv[i];        const float* p0 = vb + ((size_t)s_idx[i] << 8);
            float w1 = s_wv[i + 4];    const float* p1 = vb + ((size_t)s_idx[i + 4] << 8);
            float w2 = s_wv[i + 8];    const float* p2 = vb + ((size_t)s_idx[i + 8] << 8);
            float w3 = s_wv[i + 12];   const float* p3 = vb + ((size_t)s_idx[i + 12] << 8);
            float4 a0 = *(const float4*)(p0 + l4);
            float4 a1 = *(const float4*)(p0 + 128 + l4);
            float4 b0 = *(const float4*)(p1 + l4);
            float4 b1 = *(const float4*)(p1 + 128 + l4);
            float4 c0 = *(const float4*)(p2 + l4);
            float4 c1 = *(const float4*)(p2 + 128 + l4);
            float4 d0 = *(const float4*)(p3 + l4);
            float4 d1 = *(const float4*)(p3 + 128 + l4);
            acc0.x = fmaf(w0, a0.x, acc0.x); acc0.y = fmaf(w0, a0.y, acc0.y);
            acc0.z = fmaf(w0, a0.z, acc0.z); acc0.w = fmaf(w0, a0.w, acc0.w);
            acc1.x = fmaf(w0, a1.x, acc1.x); acc1.y = fmaf(w0, a1.y, acc1.y);
            acc1.z = fmaf(w0, a1.z, acc1.z); acc1.w = fmaf(w0, a1.w, acc1.w);
            acc0.x = fmaf(w1, b0.x, acc0.x); acc0.y = fmaf(w1, b0.y, acc0.y);
            acc0.z = fmaf(w1, b0.z, acc0.z); acc0.w = fmaf(w1, b0.w, acc0.w);
            acc1.x = fmaf(w1, b1.x, acc1.x); acc1.y = fmaf(w1, b1.y, acc1.y);
            acc1.z = fmaf(w1, b1.z, acc1.z); acc1.w = fmaf(w1, b1.w, acc1.w);
            acc0.x = fmaf(w2, c0.x, acc0.x); acc0.y = fmaf(w2, c0.y, acc0.y);
            acc0.z = fmaf(w2, c0.z, acc0.z); acc0.w = fmaf(w2, c0.w, acc0.w);
            acc1.x = fmaf(w2, c1.x, acc1.x); acc1.y = fmaf(w2, c1.y, acc1.y);
            acc1.z = fmaf(w2, c1.z, acc1.z); acc1.w = fmaf(w2, c1.w, acc1.w);
            acc0.x = fmaf(w3, d0.x, acc0.x); acc0.y = fmaf(w3, d0.y, acc0.y);
            acc0.z = fmaf(w3, d0.z, acc0.z); acc0.w = fmaf(w3, d0.w, acc0.w);
            acc1.x = fmaf(w3, d1.x, acc1.x); acc1.y = fmaf(w3, d1.y, acc1.y);
            acc1.z = fmaf(w3, d1.z, acc1.z); acc1.w = fmaf(w3, d1.w, acc1.w);
        }
        for (; i < nnz; i += 4) {
            float w = s_wv[i];
            const float* vr = vb + ((size_t)s_idx[i] << 8);
            float4 a0 = *(const float4*)(vr + l4);
            float4 a1 = *(const float4*)(vr + 128 + l4);
            acc0.x = fmaf(w, a0.x, acc0.x); acc0.y = fmaf(w, a0.y, acc0.y);
            acc0.z = fmaf(w, a0.z, acc0.z); acc0.w = fmaf(w, a0.w, acc0.w);
            acc1.x = fmaf(w, a1.x, acc1.x); acc1.y = fmaf(w, a1.y, acc1.y);
            acc1.z = fmaf(w, a1.z, acc1.z); acc1.w = fmaf(w, a1.w, acc1.w);
        }
    }
    __syncthreads();   // s_u reuse (hist -> part)
    *(float4*)&s_u.part[wrp][l4] = acc0;
    *(float4*)&s_u.part[wrp][128 + l4] = acc1;
    __syncthreads();

    float* o = out + (size_t)rowid * D_DIM;
    float r0 = s_u.part[0][tid] + s_u.part[1][tid] + s_u.part[2][tid] + s_u.part[3][tid];
    float r1 = s_u.part[0][tid + 128] + s_u.part[1][tid + 128] +
               s_u.part[2][tid + 128] + s_u.part[3][tid + 128];
    o[tid] = r0 * Zinv;
    o[tid + 128] = r1 * Zinv;
}

// ============================ launch ============================

extern "C" void kernel_launch(void* const* d_in, const int* in_sizes, int n_in,
                              void* d_out, int out_size) {
    const float* q  = (const float*)d_in[0];
    const float* k  = (const float*)d_in[1];
    const float* v  = (const float*)d_in[2];
    const int*   vl = (const int*)d_in[3];
    float* out = (float*)d_out;

    cudaFuncSetAttribute(sa_gemm_scores, cudaFuncAttributeMaxDynamicSharedMemorySize, SMEM_BYTES);

    sa_preconvert<<<(int)(QK_ELEMS / 4 / 256), 256>>>(q, k);
    dim3 g1(K_DIM / 128, Q_DIM / 128, B_DIM);   // (16, 16, 8)
    sa_gemm_scores<<<g1, 256, SMEM_BYTES>>>(vl);
    sa_topk_softmax_av<<<B_DIM * Q_DIM, 128>>>(q, k, v, vl, out);
}